// round 17
// baseline (speedup 1.0000x reference)
#include <cuda_runtime.h>
#include <cuda_fp16.h>

#define NMAX 50000
#define NG 512
#define PITCH 65   // sA pitch: (r*65+k) % 32 = (r+k)%32 -> conflict-free column reads

// ---- scratch (static __device__: no allocation allowed) ----
__device__ __align__(16) __half g_xh[NMAX * 64];   // x in half
__device__ __align__(16) __half g_aggh[NMAX * 64]; // neighbor-sum accumulator (half)
__device__ __align__(16) __half g_hh[NMAX * 64];   // hidden after Linear1 (half)
__device__ float    g_stats[128];         // [0:64) sum, [64:128) sumsq (fp32)
__device__ float    g_add[NG * 64];       // segment sum pool
__device__ unsigned g_max[NG * 64];       // segment max pool (relu>=0 -> uint order ok)
__device__ int      g_isI32;              // 1 if indices are int32, 0 if int64

// ---- packed f32x2 helpers (bit-identical fp32 math, 2 FMA/instr) ----
__device__ __forceinline__ unsigned long long pack2(float a, float b) {
    unsigned long long r;
    asm("mov.b64 %0, {%1, %2};" : "=l"(r) : "f"(a), "f"(b));
    return r;
}
__device__ __forceinline__ void unpack2(unsigned long long v, float& a, float& b) {
    asm("mov.b64 {%0, %1}, %2;" : "=f"(a), "=f"(b) : "l"(v));
}
#define FMA2(acc, a2, b2) \
    asm("fma.rn.f32x2 %0, %1, %2, %3;" : "=l"(acc) : "l"(a2), "l"(b2), "l"(acc))

// ============================================================
// K0: pack x->half, zero accumulator/stats/pools, probe idx dtype
// ============================================================
__global__ void k_init(const float* __restrict__ x, const int* __restrict__ ei32, int n8) {
    int tid = blockIdx.x * blockDim.x + threadIdx.x;
    if (tid == 0) {
        int nz = 0;
        #pragma unroll 4
        for (int i = 0; i < 256; i++) nz |= ei32[2 * i + 1];
        g_isI32 = (nz != 0) ? 1 : 0;
    }
    if (tid < n8) {
        const float4* xp = (const float4*)(x + (size_t)tid * 8);
        float4 a = xp[0], b = xp[1];
        __half2 h0 = __float22half2_rn(make_float2(a.x, a.y));
        __half2 h1 = __float22half2_rn(make_float2(a.z, a.w));
        __half2 h2 = __float22half2_rn(make_float2(b.x, b.y));
        __half2 h3 = __float22half2_rn(make_float2(b.z, b.w));
        uint4 o;
        o.x = *(unsigned*)&h0; o.y = *(unsigned*)&h1;
        o.z = *(unsigned*)&h2; o.w = *(unsigned*)&h3;
        *(uint4*)(g_xh + (size_t)tid * 8) = o;
        *(uint4*)(g_aggh + (size_t)tid * 8) = make_uint4(0u, 0u, 0u, 0u);
    }
    if (tid < 128) g_stats[tid] = 0.0f;
    if (tid < NG * 64) { g_add[tid] = 0.0f; g_max[tid] = 0u; }
}

// ============================================================
// K1: edge scatter  aggh[dst] += xh[src]
// ============================================================
__global__ void k_edges(const void* __restrict__ ei, int n_edges) {
    int tid = blockIdx.x * blockDim.x + threadIdx.x;
    if (tid >= n_edges * 8) return;
    int e = tid >> 3;
    int c = tid & 7;
    int s, d;
    if (g_isI32) {
        const int* p = (const int*)ei;
        s = p[e]; d = p[n_edges + e];
    } else {
        const long long* p = (const long long*)ei;
        s = (int)p[e]; d = (int)p[n_edges + e];
    }
    uint4 v = *(const uint4*)(g_xh + ((size_t)s << 6) + (c << 3));
    __half* o = g_aggh + ((size_t)d << 6) + (c << 3);
    asm volatile("red.global.add.noftz.v4.f16x2 [%0], {%1, %2, %3, %4};"
                 :: "l"(o), "r"(v.x), "r"(v.y), "r"(v.z), "r"(v.w)
                 : "memory");
}

// ---- GEMM inner loop: 1 row x 16 cols / thread
//      A: 1 scalar LDS, 32 distinct banks (pitch 65) -> 1 phase
//      W: 4x LDS.128 uniform across warp -> broadcast
#define GEMM_CORE16(sA, sW, acc, r, c0)                                      \
    _Pragma("unroll 16")                                                     \
    for (int k = 0; k < 64; k++) {                                           \
        float a = sA[r * PITCH + k];                                         \
        ulonglong2 wa = *(const ulonglong2*)&sW[k * 64 + c0];                \
        ulonglong2 wb = *(const ulonglong2*)&sW[k * 64 + c0 + 4];            \
        ulonglong2 wc = *(const ulonglong2*)&sW[k * 64 + c0 + 8];            \
        ulonglong2 wd = *(const ulonglong2*)&sW[k * 64 + c0 + 12];           \
        unsigned long long aa = pack2(a, a);                                 \
        FMA2(acc[0], aa, wa.x); FMA2(acc[1], aa, wa.y);                      \
        FMA2(acc[2], aa, wb.x); FMA2(acc[3], aa, wb.y);                      \
        FMA2(acc[4], aa, wc.x); FMA2(acc[5], aa, wc.y);                      \
        FMA2(acc[6], aa, wd.x); FMA2(acc[7], aa, wd.y);                      \
    }

// ============================================================
// K2: h = (x + aggh) @ W1 + b1, BN sum/sumsq (fp32), store h half
// ============================================================
__global__ __launch_bounds__(256, 6) void k_gemm1(const float* __restrict__ x,
                                                  const float* __restrict__ W1,
                                                  const float* __restrict__ b1, int n_nodes) {
    __shared__ float sW[64 * 64];
    __shared__ float sA[64 * PITCH];
    __shared__ float sSum[64], sSq[64];
    int tid = threadIdx.x;
    int row0 = blockIdx.x * 64;

    for (int i = tid; i < 1024; i += 256) ((float4*)sW)[i] = ((const float4*)W1)[i];
    if (tid < 64) { sSum[tid] = 0.0f; sSq[tid] = 0.0f; }
    for (int i = tid; i < 1024; i += 256) {
        int r = i >> 4, c4 = i & 15, gr = row0 + r;
        float4 v = make_float4(0.f, 0.f, 0.f, 0.f);
        if (gr < n_nodes) {
            v = *(const float4*)(x + (size_t)gr * 64 + c4 * 4);
            uint2 hh = *(const uint2*)(g_aggh + (size_t)gr * 64 + c4 * 4);
            float2 f0 = __half22float2(*(__half2*)&hh.x);
            float2 f1 = __half22float2(*(__half2*)&hh.y);
            v.x += f0.x; v.y += f0.y; v.z += f1.x; v.w += f1.y;
        }
        float* p = &sA[r * PITCH + c4 * 4];
        p[0] = v.x; p[1] = v.y; p[2] = v.z; p[3] = v.w;
    }
    __syncthreads();

    int r = tid & 63;
    int c0 = (tid >> 6) * 16;
    unsigned long long acc[8];
    {
        float4 bA = *(const float4*)(b1 + c0);
        float4 bB = *(const float4*)(b1 + c0 + 4);
        float4 bC = *(const float4*)(b1 + c0 + 8);
        float4 bD = *(const float4*)(b1 + c0 + 12);
        acc[0] = pack2(bA.x, bA.y); acc[1] = pack2(bA.z, bA.w);
        acc[2] = pack2(bB.x, bB.y); acc[3] = pack2(bB.z, bB.w);
        acc[4] = pack2(bC.x, bC.y); acc[5] = pack2(bC.z, bC.w);
        acc[6] = pack2(bD.x, bD.y); acc[7] = pack2(bD.z, bD.w);
    }

    GEMM_CORE16(sA, sW, acc, r, c0)

    int gr = row0 + r;
    float f[16];
    #pragma unroll
    for (int j = 0; j < 8; j++) unpack2(acc[j], f[2 * j], f[2 * j + 1]);
    if (gr < n_nodes) {
        uint4 st0, st1;
        __half2 p0 = __float22half2_rn(make_float2(f[0], f[1]));
        __half2 p1 = __float22half2_rn(make_float2(f[2], f[3]));
        __half2 p2 = __float22half2_rn(make_float2(f[4], f[5]));
        __half2 p3 = __float22half2_rn(make_float2(f[6], f[7]));
        __half2 p4 = __float22half2_rn(make_float2(f[8], f[9]));
        __half2 p5 = __float22half2_rn(make_float2(f[10], f[11]));
        __half2 p6 = __float22half2_rn(make_float2(f[12], f[13]));
        __half2 p7 = __float22half2_rn(make_float2(f[14], f[15]));
        st0.x = *(unsigned*)&p0; st0.y = *(unsigned*)&p1;
        st0.z = *(unsigned*)&p2; st0.w = *(unsigned*)&p3;
        st1.x = *(unsigned*)&p4; st1.y = *(unsigned*)&p5;
        st1.z = *(unsigned*)&p6; st1.w = *(unsigned*)&p7;
        *(uint4*)(g_hh + (size_t)gr * 64 + c0) = st0;
        *(uint4*)(g_hh + (size_t)gr * 64 + c0 + 8) = st1;
        #pragma unroll
        for (int j = 0; j < 16; j++) {
            atomicAdd(&sSum[c0 + j], f[j]);
            atomicAdd(&sSq[c0 + j], f[j] * f[j]);
        }
    }
    __syncthreads();
    if (tid < 64) {
        atomicAdd(&g_stats[tid], sSum[tid]);
        atomicAdd(&g_stats[64 + tid], sSq[tid]);
    }
}

// ============================================================
// K4: h2 = relu(relu(bn(h)) @ W2 + b2); pooled into g_add/g_max
// ============================================================
__global__ __launch_bounds__(256, 6) void k_gemm2(const float* __restrict__ W2,
                                                  const float* __restrict__ b2,
                                                  const float* __restrict__ gamma,
                                                  const float* __restrict__ beta,
                                                  const void* __restrict__ batch,
                                                  int n_nodes, float inv_n) {
    __shared__ float sW[64 * 64];
    __shared__ float sA[64 * PITCH];
    __shared__ float sScale[64], sShift[64];
    int tid = threadIdx.x;
    int row0 = blockIdx.x * 64;

    for (int i = tid; i < 1024; i += 256) ((float4*)sW)[i] = ((const float4*)W2)[i];
    if (tid < 64) {
        float mean = g_stats[tid] * inv_n;
        float var  = g_stats[64 + tid] * inv_n - mean * mean;
        float a = gamma[tid] * rsqrtf(var + 1e-5f);
        sScale[tid] = a;
        sShift[tid] = beta[tid] - mean * a;
    }
    __syncthreads();
    for (int i = tid; i < 1024; i += 256) {
        int r = i >> 4, c4 = i & 15, gr = row0 + r, k0 = c4 * 4;
        float4 v = make_float4(0.f, 0.f, 0.f, 0.f);
        if (gr < n_nodes) {
            uint2 hh = *(const uint2*)(g_hh + (size_t)gr * 64 + k0);
            float2 f0 = __half22float2(*(__half2*)&hh.x);
            float2 f1 = __half22float2(*(__half2*)&hh.y);
            v.x = fmaxf(f0.x * sScale[k0 + 0] + sShift[k0 + 0], 0.f);
            v.y = fmaxf(f0.y * sScale[k0 + 1] + sShift[k0 + 1], 0.f);
            v.z = fmaxf(f1.x * sScale[k0 + 2] + sShift[k0 + 2], 0.f);
            v.w = fmaxf(f1.y * sScale[k0 + 3] + sShift[k0 + 3], 0.f);
        }
        float* p = &sA[r * PITCH + k0];
        p[0] = v.x; p[1] = v.y; p[2] = v.z; p[3] = v.w;
    }
    __syncthreads();

    int r = tid & 63;
    int c0 = (tid >> 6) * 16;
    unsigned long long acc[8];
    {
        float4 bA = *(const float4*)(b2 + c0);
        float4 bB = *(const float4*)(b2 + c0 + 4);
        float4 bC = *(const float4*)(b2 + c0 + 8);
        float4 bD = *(const float4*)(b2 + c0 + 12);
        acc[0] = pack2(bA.x, bA.y); acc[1] = pack2(bA.z, bA.w);
        acc[2] = pack2(bB.x, bB.y); acc[3] = pack2(bB.z, bB.w);
        acc[4] = pack2(bC.x, bC.y); acc[5] = pack2(bC.z, bC.w);
        acc[6] = pack2(bD.x, bD.y); acc[7] = pack2(bD.z, bD.w);
    }

    GEMM_CORE16(sA, sW, acc, r, c0)

    int gr = row0 + r;
    if (gr < n_nodes) {
        int b = g_isI32 ? ((const int*)batch)[gr] : (int)((const long long*)batch)[gr];
        float f[16];
        #pragma unroll
        for (int j = 0; j < 8; j++) unpack2(acc[j], f[2 * j], f[2 * j + 1]);
        #pragma unroll
        for (int j = 0; j < 16; j++) f[j] = fmaxf(f[j], 0.f);
        float* pa = g_add + (size_t)b * 64 + c0;
        #pragma unroll
        for (int q = 0; q < 4; q++) {
            asm volatile("red.global.add.v4.f32 [%0], {%1, %2, %3, %4};"
                         :: "l"(pa + q * 4), "f"(f[4 * q]), "f"(f[4 * q + 1]),
                            "f"(f[4 * q + 2]), "f"(f[4 * q + 3]) : "memory");
        }
        unsigned* pm = g_max + (size_t)b * 64 + c0;
        #pragma unroll
        for (int j = 0; j < 16; j++) atomicMax(pm + j, __float_as_uint(f[j]));
    }
}

// ============================================================
// K5: head MLP, 8 graphs per block
// ============================================================
__global__ __launch_bounds__(128) void k_final(const float* __restrict__ Wl1,
                                               const float* __restrict__ bl1,
                                               const float* __restrict__ Wl2,
                                               const float* __restrict__ bl2,
                                               float* __restrict__ out, int out_size) {
    int g0 = blockIdx.x * 8;
    int j = threadIdx.x;
    __shared__ float sg[8][128];
    __shared__ float red[8][128];
    #pragma unroll
    for (int q = 0; q < 8; q++) {
        int g = g0 + q;
        sg[q][j] = (j < 64) ? g_add[g * 64 + j]
                            : __uint_as_float(g_max[g * 64 + (j - 64)]);
    }
    __syncthreads();
    float bj = bl1[j];
    float t[8];
    #pragma unroll
    for (int q = 0; q < 8; q++) t[q] = bj;
    #pragma unroll 4
    for (int k = 0; k < 128; k++) {
        float w = Wl1[k * 128 + j];
        #pragma unroll
        for (int q = 0; q < 8; q++) t[q] += sg[q][k] * w;
    }
    float w2 = Wl2[j];
    #pragma unroll
    for (int q = 0; q < 8; q++) red[q][j] = fmaxf(t[q], 0.f) * w2;
    __syncthreads();
    for (int sft = 64; sft > 0; sft >>= 1) {
        if (j < sft) {
            #pragma unroll
            for (int q = 0; q < 8; q++) red[q][j] += red[q][j + sft];
        }
        __syncthreads();
    }
    if (j < 8) {
        float logit = red[j][0] + bl2[0];
        int g = g0 + j;
        out[g] = 1.0f / (1.0f + expf(-logit));
        if (out_size >= 2 * NG) out[NG + g] = logit;
    }
}

// ============================================================
extern "C" void kernel_launch(void* const* d_in, const int* in_sizes, int n_in,
                              void* d_out, int out_size) {
    const float* x     = (const float*)d_in[0];
    const void*  ei    = d_in[1];
    const void*  batch = d_in[2];
    const float* W1    = (const float*)d_in[3];
    const float* b1    = (const float*)d_in[4];
    const float* gamma = (const float*)d_in[5];
    const float* beta  = (const float*)d_in[6];
    const float* W2    = (const float*)d_in[7];
    const float* b2    = (const float*)d_in[8];
    const float* Wl1   = (const float*)d_in[9];
    const float* bl1   = (const float*)d_in[10];
    const float* Wl2   = (const float*)d_in[11];
    const float* bl2   = (const float*)d_in[12];
    float* out = (float*)d_out;

    int n_nodes = in_sizes[0] / 64;
    if (n_nodes > NMAX) n_nodes = NMAX;
    int n_edges = in_sizes[1] / 2;

    int n8 = n_nodes * 8;
    int initN = (n8 > NG * 64) ? n8 : NG * 64;
    k_init<<<(initN + 255) / 256, 256>>>(x, (const int*)ei, n8);

    long long etot = (long long)n_edges * 8;
    k_edges<<<(int)((etot + 255) / 256), 256>>>(ei, n_edges);

    int nb = (n_nodes + 63) / 64;
    k_gemm1<<<nb, 256>>>(x, W1, b1, n_nodes);
    k_gemm2<<<nb, 256>>>(W2, b2, gamma, beta, batch, n_nodes, 1.0f / (float)n_nodes);
    k_final<<<NG / 8, 128>>>(Wl1, bl1, Wl2, bl2, out, out_size);
}